// round 12
// baseline (speedup 1.0000x reference)
#include <cuda_runtime.h>
#include <cuda_bf16.h>
#include <cstdint>

#define N_NODES 50000
#define N_EDGES 800000
#define IN_DIM  256
#define OUT_DIM 64
#define NEG_SLOPE 0.01f
#define TILE_M 64
#define N_TILES ((N_NODES + TILE_M - 1) / TILE_M)

typedef unsigned long long ull;

// ---------------- device scratch ----------------
__device__ float g_z[N_NODES * OUT_DIM];     // 12.8 MB, L2-resident
__device__ float g_sl[N_NODES];
__device__ float g_sr[N_NODES];
__device__ int   g_cnt[N_NODES];             // per-dst counts (self-cleaned by scan)
__device__ int   g_off[N_NODES + 1];         // CSR offsets
__device__ int   g_cur[N_NODES];             // scatter cursors
__device__ int   g_ssrc[N_EDGES];            // src ids sorted by dst
__device__ unsigned g_barA[3];               // grid barrier arrive counters
__device__ unsigned g_barL[3];               // grid barrier leave counters

__device__ __forceinline__ uint32_t smem_u32(const void* p) {
    uint32_t a;
    asm("{ .reg .u64 t; cvta.to.shared.u64 t, %1; cvt.u32.u64 %0, t; }" : "=r"(a) : "l"(p));
    return a;
}

// Software grid barrier (all CTAs co-resident by construction).
// Self-resetting: last leaver restores zeros -> safe across graph replays.
__device__ __forceinline__ void gridbar(int i, int nCTA) {
    __threadfence();
    __syncthreads();
    if (threadIdx.x == 0) {
        atomicAdd(&g_barA[i], 1u);
        while (*((volatile unsigned*)&g_barA[i]) < (unsigned)nCTA) { }
        __threadfence();
        unsigned l = atomicAdd(&g_barL[i], 1u);
        if (l == (unsigned)(nCTA - 1)) {
            g_barA[i] = 0u;
            g_barL[i] = 0u;
            __threadfence();
        }
    }
    __syncthreads();
}

#define LDSM4(R, addr) \
    asm volatile("ldmatrix.sync.aligned.m8n8.x4.shared.b16 {%0,%1,%2,%3}, [%4];" \
        : "=r"((R)[0]), "=r"((R)[1]), "=r"((R)[2]), "=r"((R)[3]) : "r"(addr))
#define LDSM4T(R, addr) \
    asm volatile("ldmatrix.sync.aligned.m8n8.x4.trans.shared.b16 {%0,%1,%2,%3}, [%4];" \
        : "=r"((R)[0]), "=r"((R)[1]), "=r"((R)[2]), "=r"((R)[3]) : "r"(addr))
#define MMA16816(D, A, b0, b1) \
    asm volatile("mma.sync.aligned.m16n8k16.row.col.f32.bf16.bf16.f32 " \
        "{%0,%1,%2,%3}, {%4,%5,%6,%7}, {%8,%9}, {%0,%1,%2,%3};" \
        : "+f"((D)[0]), "+f"((D)[1]), "+f"((D)[2]), "+f"((D)[3]) \
        : "r"((A)[0]), "r"((A)[1]), "r"((A)[2]), "r"((A)[3]), "r"(b0), "r"(b1))

// ---------------- SMEM layout (bytes) ----------------
#define W_STRIDE_B 144
#define A_STRIDE_B 272
#define SM_WHI   0
#define SM_WLO   36864
#define SM_AHI   73728
#define SM_ALO   91136
#define SM_SLR   108544
#define SM_TOTAL 109568

// ---------------- the megakernel ----------------
__global__ void __launch_bounds__(256, 2) mega_kernel(
    const float* __restrict__ h,
    const float* __restrict__ W,
    const float* __restrict__ a_attn,
    const int*   __restrict__ edge_src,
    const int*   __restrict__ edge_dst,
    float*       __restrict__ out,
    int nCTA)
{
    extern __shared__ char smem[];
    const uint32_t sb = smem_u32(smem);
    const int cta = blockIdx.x;
    const int t = threadIdx.x, wid = t >> 5, lane = t & 31;

    // ================= PHASE A0: edge histogram (hides inside gemm phase) =================
    for (int i = cta * 256 + t; i < N_EDGES / 4; i += nCTA * 256) {
        int4 d = ((const int4*)edge_dst)[i];
        atomicAdd(&g_cnt[d.x], 1);
        atomicAdd(&g_cnt[d.y], 1);
        atomicAdd(&g_cnt[d.z], 1);
        atomicAdd(&g_cnt[d.w], 1);
    }

    // ---- W convert fp32 -> bf16 hi/lo into smem (ONCE per CTA, resident across tiles) ----
    for (int i = t; i < IN_DIM * OUT_DIM; i += 256) {
        int k = i >> 6, n = i & 63;
        float w = W[i];
        __nv_bfloat16 wh = __float2bfloat16(w);
        __nv_bfloat16 wl = __float2bfloat16(w - __bfloat162float(wh));
        *(__nv_bfloat16*)(smem + SM_WHI + k * W_STRIDE_B + n * 2) = wh;
        *(__nv_bfloat16*)(smem + SM_WLO + k * W_STRIDE_B + n * 2) = wl;
    }
    __syncthreads();

    // ================= PHASE A1: gemm tiles (R9-proven body) =================
    const int wm = wid & 3, wn = wid >> 2;
    const int m0 = wm * 16;
    const int lr = lane & 7, lh = (lane >> 3) & 1, lq = lane >> 4;

    const uint32_t aHiBase = sb + SM_AHI + (uint32_t)(m0 + lr + lh * 8) * A_STRIDE_B + lq * 16;
    const uint32_t aLoBase = aHiBase + (SM_ALO - SM_AHI);
    const uint32_t bHiBase = sb + SM_WHI + (uint32_t)(lr + lh * 8) * W_STRIDE_B + wn * 64 + lq * 16;
    const uint32_t bLoBase = bHiBase + (SM_WLO - SM_WHI);

    for (int tile = cta; tile < N_TILES; tile += nCTA) {
        const int row0 = tile * TILE_M;

        float d[4][4];
        #pragma unroll
        for (int i = 0; i < 4; i++)
            #pragma unroll
            for (int j = 0; j < 4; j++) d[i][j] = 0.f;

        #pragma unroll 1
        for (int chunk = 0; chunk < 2; chunk++) {
            #pragma unroll
            for (int i = t; i < TILE_M * 32; i += 256) {
                int r = i >> 5, k4 = i & 31;
                int gr = row0 + r;
                float4 v = (gr < N_NODES)
                         ? ((const float4*)h)[gr * (IN_DIM / 4) + chunk * 32 + k4]
                         : make_float4(0.f, 0.f, 0.f, 0.f);
                __nv_bfloat162 h01 = __floats2bfloat162_rn(v.x, v.y);
                __nv_bfloat162 h23 = __floats2bfloat162_rn(v.z, v.w);
                __nv_bfloat162 l01 = __floats2bfloat162_rn(v.x - __bfloat162float(h01.x),
                                                           v.y - __bfloat162float(h01.y));
                __nv_bfloat162 l23 = __floats2bfloat162_rn(v.z - __bfloat162float(h23.x),
                                                           v.w - __bfloat162float(h23.y));
                uint32_t off = (uint32_t)r * A_STRIDE_B + k4 * 8;
                *(uint2*)(smem + SM_AHI + off) = make_uint2(*(uint32_t*)&h01, *(uint32_t*)&h23);
                *(uint2*)(smem + SM_ALO + off) = make_uint2(*(uint32_t*)&l01, *(uint32_t*)&l23);
            }
            __syncthreads();

            #pragma unroll 2
            for (int kcl = 0; kcl < 8; kcl++) {
                int kcg = chunk * 8 + kcl;
                uint32_t ah[4], al[4];
                LDSM4(ah, aHiBase + kcl * 32);
                LDSM4(al, aLoBase + kcl * 32);
                uint32_t bh[2][4], bl[2][4];
                #pragma unroll
                for (int j = 0; j < 2; j++) {
                    LDSM4T(bh[j], bHiBase + kcg * (16 * W_STRIDE_B) + j * 32);
                    LDSM4T(bl[j], bLoBase + kcg * (16 * W_STRIDE_B) + j * 32);
                }
                #pragma unroll
                for (int j = 0; j < 2; j++) {
                    MMA16816(d[2 * j],     ah, bh[j][0], bh[j][1]);
                    MMA16816(d[2 * j],     ah, bl[j][0], bl[j][1]);
                    MMA16816(d[2 * j],     al, bh[j][0], bh[j][1]);
                    MMA16816(d[2 * j + 1], ah, bh[j][2], bh[j][3]);
                    MMA16816(d[2 * j + 1], ah, bl[j][2], bl[j][3]);
                    MMA16816(d[2 * j + 1], al, bh[j][2], bh[j][3]);
                }
            }
            __syncthreads();
        }

        // ---- tile epilogue: z + fused s_l/s_r ----
        float* slr = (float*)(smem + SM_SLR);
        const int q = lane >> 2, cq = (lane & 3) * 2;
        const int r1 = row0 + m0 + q, r2 = r1 + 8;
        float sl1 = 0.f, sr1 = 0.f, sl2 = 0.f, sr2 = 0.f;
        #pragma unroll
        for (int i = 0; i < 4; i++) {
            int c = wn * 32 + i * 8 + cq;
            float a0 = __ldg(&a_attn[c]),      a1 = __ldg(&a_attn[c + 1]);
            float b0 = __ldg(&a_attn[64 + c]), b1 = __ldg(&a_attn[64 + c + 1]);
            sl1 += d[i][0] * a0 + d[i][1] * a1;
            sr1 += d[i][0] * b0 + d[i][1] * b1;
            sl2 += d[i][2] * a0 + d[i][3] * a1;
            sr2 += d[i][2] * b0 + d[i][3] * b1;
            if (r1 < N_NODES) *(float2*)&g_z[r1 * OUT_DIM + c] = make_float2(d[i][0], d[i][1]);
            if (r2 < N_NODES) *(float2*)&g_z[r2 * OUT_DIM + c] = make_float2(d[i][2], d[i][3]);
        }
        #pragma unroll
        for (int o = 1; o < 4; o <<= 1) {
            sl1 += __shfl_xor_sync(0xffffffffu, sl1, o);
            sr1 += __shfl_xor_sync(0xffffffffu, sr1, o);
            sl2 += __shfl_xor_sync(0xffffffffu, sl2, o);
            sr2 += __shfl_xor_sync(0xffffffffu, sr2, o);
        }
        if ((lane & 3) == 0) {
            *(float2*)&slr[(m0 + q)     * 4 + wn * 2] = make_float2(sl1, sr1);
            *(float2*)&slr[(m0 + q + 8) * 4 + wn * 2] = make_float2(sl2, sr2);
        }
        __syncthreads();
        if (t < TILE_M) {
            int row = row0 + t;
            if (row < N_NODES) {
                g_sl[row] = slr[t * 4 + 0] + slr[t * 4 + 2];
                g_sr[row] = slr[t * 4 + 1] + slr[t * 4 + 3];
            }
        }
        __syncthreads();
    }

    gridbar(0, nCTA);

    // ================= PHASE B: scan (CTA 0; also self-cleans g_cnt) =================
    if (cta == 0) {
        const int C = 196;                      // 256*196 = 50176 >= 50000
        int* wsum = (int*)(smem + SM_SLR);
        const int base = t * C;
        int s = 0;
        for (int i = 0; i < C; i++) {
            int n = base + i;
            if (n < N_NODES) s += g_cnt[n];
        }
        int x = s;
        #pragma unroll
        for (int o = 1; o < 32; o <<= 1) {
            int y = __shfl_up_sync(0xffffffffu, x, o);
            if (lane >= o) x += y;
        }
        if (lane == 31) wsum[wid] = x;
        __syncthreads();
        if (wid == 0 && lane < 8) {
            int v = wsum[lane];
            #pragma unroll
            for (int o = 1; o < 8; o <<= 1) {
                int y = __shfl_up_sync(0x000000ffu, v, o);
                if (lane >= o) v += y;
            }
            wsum[lane] = v;
        }
        __syncthreads();
        int run = x - s + ((wid > 0) ? wsum[wid - 1] : 0);
        for (int i = 0; i < C; i++) {
            int n = base + i;
            if (n < N_NODES) {
                int c = g_cnt[n];
                g_cnt[n] = 0;                   // self-clean for next replay
                g_off[n] = run;
                g_cur[n] = run;
                run += c;
            }
        }
        if (t == 0) g_off[N_NODES] = N_EDGES;
    }

    gridbar(1, nCTA);

    // ================= PHASE C: permutation scatter =================
    for (int i = cta * 256 + t; i < N_EDGES / 4; i += nCTA * 256) {
        int4 s4 = ((const int4*)edge_src)[i];
        int4 d4 = ((const int4*)edge_dst)[i];
        int p0 = atomicAdd(&g_cur[d4.x], 1);
        int p1 = atomicAdd(&g_cur[d4.y], 1);
        int p2 = atomicAdd(&g_cur[d4.z], 1);
        int p3 = atomicAdd(&g_cur[d4.w], 1);
        g_ssrc[p0] = s4.x;
        g_ssrc[p1] = s4.y;
        g_ssrc[p2] = s4.z;
        g_ssrc[p3] = s4.w;
    }

    gridbar(2, nCTA);

    // ================= PHASE D: node softmax + gather (one warp per dst) =================
    for (int gw = cta * 8 + wid; gw < N_NODES; gw += nCTA * 8) {
        int beg = g_off[gw];
        int end = g_off[gw + 1];

        float2 acc = make_float2(0.f, 0.f);
        if (beg < end) {
            const float srg = g_sr[gw];
            float den = 0.f;
            for (int j = beg + lane; j < end; j += 32) {
                float e = g_sl[g_ssrc[j]] + srg;
                e = (e > 0.f) ? e : NEG_SLOPE * e;
                den += __expf(e);
            }
            #pragma unroll
            for (int o = 16; o; o >>= 1) den += __shfl_xor_sync(0xffffffffu, den, o);
            float invden = 1.0f / den;

            int j = beg;
            for (; j + 3 < end; j += 4) {
                int s0 = g_ssrc[j],     s1 = g_ssrc[j + 1];
                int s2 = g_ssrc[j + 2], s3 = g_ssrc[j + 3];
                float e0 = g_sl[s0] + srg, e1 = g_sl[s1] + srg;
                float e2 = g_sl[s2] + srg, e3 = g_sl[s3] + srg;
                float2 z0 = *(const float2*)&g_z[s0 * OUT_DIM + 2 * lane];
                float2 z1 = *(const float2*)&g_z[s1 * OUT_DIM + 2 * lane];
                float2 z2 = *(const float2*)&g_z[s2 * OUT_DIM + 2 * lane];
                float2 z3 = *(const float2*)&g_z[s3 * OUT_DIM + 2 * lane];
                e0 = (e0 > 0.f) ? e0 : NEG_SLOPE * e0;
                e1 = (e1 > 0.f) ? e1 : NEG_SLOPE * e1;
                e2 = (e2 > 0.f) ? e2 : NEG_SLOPE * e2;
                e3 = (e3 > 0.f) ? e3 : NEG_SLOPE * e3;
                float a0 = __expf(e0) * invden;
                float a1 = __expf(e1) * invden;
                float a2 = __expf(e2) * invden;
                float a3 = __expf(e3) * invden;
                acc.x += a0 * z0.x + a1 * z1.x + a2 * z2.x + a3 * z3.x;
                acc.y += a0 * z0.y + a1 * z1.y + a2 * z2.y + a3 * z3.y;
            }
            for (; j < end; ++j) {
                int s0 = g_ssrc[j];
                float e0 = g_sl[s0] + srg;
                e0 = (e0 > 0.f) ? e0 : NEG_SLOPE * e0;
                float a0 = __expf(e0) * invden;
                float2 z0 = *(const float2*)&g_z[s0 * OUT_DIM + 2 * lane];
                acc.x += a0 * z0.x;
                acc.y += a0 * z0.y;
            }
        }
        *(float2*)&out[gw * OUT_DIM + 2 * lane] = acc;
    }
}

// ---------------- launch: ONE graph node ----------------
extern "C" void kernel_launch(void* const* d_in, const int* in_sizes, int n_in,
                              void* d_out, int out_size) {
    const float* h        = (const float*)d_in[0];
    const int*   edge_src = (const int*)d_in[1];
    const int*   edge_dst = (const int*)d_in[2];
    const float* W_fc     = (const float*)d_in[3];
    const float* a_attn   = (const float*)d_in[4];
    float* out = (float*)d_out;

    static int nCTA = 0;
    if (!nCTA) {
        cudaFuncSetAttribute(mega_kernel, cudaFuncAttributeMaxDynamicSharedMemorySize, SM_TOTAL);
        int perSM = 0;
        cudaOccupancyMaxActiveBlocksPerMultiprocessor(&perSM, mega_kernel, 256, SM_TOTAL);
        int sms = 0;
        cudaDeviceGetAttribute(&sms, cudaDevAttrMultiProcessorCount, 0);
        nCTA = perSM * sms;
        if (nCTA < 1) nCTA = 1;
    }

    mega_kernel<<<nCTA, 256, SM_TOTAL>>>(h, W_fc, a_attn, edge_src, edge_dst, out, nCTA);
}

// round 13
// speedup vs baseline: 1.1525x; 1.1525x over previous
#include <cuda_runtime.h>
#include <cuda_bf16.h>
#include <cstdint>

#define N_NODES 50000
#define N_EDGES 800000
#define IN_DIM  256
#define OUT_DIM 64
#define NEG_SLOPE 0.01f
#define TILE_M 64

typedef unsigned long long ull;

// ---------------- device scratch ----------------
__device__ float g_z[N_NODES * OUT_DIM];     // 12.8 MB, L2-resident
__device__ float g_sl[N_NODES];
__device__ float g_sr[N_NODES];
__device__ float g_den[N_NODES];
__device__ int   g_off[N_NODES + 1];
__device__ int   g_cur[N_NODES];
__device__ ull   g_ep[N_EDGES];              // packed (exp(e)<<32 | src), dst-sorted

__device__ __forceinline__ uint32_t smem_u32(const void* p) {
    uint32_t a;
    asm("{ .reg .u64 t; cvta.to.shared.u64 t, %1; cvt.u32.u64 %0, t; }" : "=r"(a) : "l"(p));
    return a;
}

#define LDSM4(R, addr) \
    asm volatile("ldmatrix.sync.aligned.m8n8.x4.shared.b16 {%0,%1,%2,%3}, [%4];" \
        : "=r"((R)[0]), "=r"((R)[1]), "=r"((R)[2]), "=r"((R)[3]) : "r"(addr))
#define LDSM4T(R, addr) \
    asm volatile("ldmatrix.sync.aligned.m8n8.x4.trans.shared.b16 {%0,%1,%2,%3}, [%4];" \
        : "=r"((R)[0]), "=r"((R)[1]), "=r"((R)[2]), "=r"((R)[3]) : "r"(addr))
#define MMA16816(D, A, b0, b1) \
    asm volatile("mma.sync.aligned.m16n8k16.row.col.f32.bf16.bf16.f32 " \
        "{%0,%1,%2,%3}, {%4,%5,%6,%7}, {%8,%9}, {%0,%1,%2,%3};" \
        : "+f"((D)[0]), "+f"((D)[1]), "+f"((D)[2]), "+f"((D)[3]) \
        : "r"((A)[0]), "r"((A)[1]), "r"((A)[2]), "r"((A)[3]), "r"(b0), "r"(b1))

// ---------------- SMEM layout (bytes) ----------------
#define W_STRIDE_B 144
#define A_STRIDE_B 272
#define SM_WHI   0
#define SM_WLO   36864
#define SM_AHI   73728
#define SM_ALO   91136
#define SM_SLR   108544
#define SM_TOTAL 109568

// ---------------- GEMM: mma.sync bf16x3, 2 CTA/SM, inline W convert ----------------
__global__ void __launch_bounds__(256, 2) gemm_kernel(const float* __restrict__ h,
                                                      const float* __restrict__ W,
                                                      const float* __restrict__ a_attn) {
    extern __shared__ char smem[];
    const uint32_t sb = smem_u32(smem);
    const int t = threadIdx.x, wid = t >> 5, lane = t & 31;
    const int row0 = blockIdx.x * TILE_M;

    // ---- convert W fp32 -> bf16 hi/lo into padded smem (R8-proven) ----
    for (int i = t; i < IN_DIM * OUT_DIM; i += 256) {
        int k = i >> 6, n = i & 63;
        float w = W[i];
        __nv_bfloat16 wh = __float2bfloat16(w);
        __nv_bfloat16 wl = __float2bfloat16(w - __bfloat162float(wh));
        *(__nv_bfloat16*)(smem + SM_WHI + k * W_STRIDE_B + n * 2) = wh;
        *(__nv_bfloat16*)(smem + SM_WLO + k * W_STRIDE_B + n * 2) = wl;
    }

    const int wm = wid & 3, wn = wid >> 2;
    const int m0 = wm * 16;
    const int lr = lane & 7, lh = (lane >> 3) & 1, lq = lane >> 4;

    const uint32_t aHiBase = sb + SM_AHI + (uint32_t)(m0 + lr + lh * 8) * A_STRIDE_B + lq * 16;
    const uint32_t aLoBase = aHiBase + (SM_ALO - SM_AHI);
    const uint32_t bHiBase = sb + SM_WHI + (uint32_t)(lr + lh * 8) * W_STRIDE_B + wn * 64 + lq * 16;
    const uint32_t bLoBase = bHiBase + (SM_WLO - SM_WHI);

    float d[4][4];
    #pragma unroll
    for (int i = 0; i < 4; i++)
        #pragma unroll
        for (int j = 0; j < 4; j++) d[i][j] = 0.f;

    #pragma unroll 1
    for (int chunk = 0; chunk < 2; chunk++) {
        #pragma unroll
        for (int i = t; i < TILE_M * 32; i += 256) {
            int r = i >> 5, k4 = i & 31;
            int gr = row0 + r;
            float4 v = (gr < N_NODES)
                     ? ((const float4*)h)[gr * (IN_DIM / 4) + chunk * 32 + k4]
                     : make_float4(0.f, 0.f, 0.f, 0.f);
            __nv_bfloat162 h01 = __floats2bfloat162_rn(v.x, v.y);
            __nv_bfloat162 h23 = __floats2bfloat162_rn(v.z, v.w);
            __nv_bfloat162 l01 = __floats2bfloat162_rn(v.x - __bfloat162float(h01.x),
                                                       v.y - __bfloat162float(h01.y));
            __nv_bfloat162 l23 = __floats2bfloat162_rn(v.z - __bfloat162float(h23.x),
                                                       v.w - __bfloat162float(h23.y));
            uint32_t off = (uint32_t)r * A_STRIDE_B + k4 * 8;
            *(uint2*)(smem + SM_AHI + off) = make_uint2(*(uint32_t*)&h01, *(uint32_t*)&h23);
            *(uint2*)(smem + SM_ALO + off) = make_uint2(*(uint32_t*)&l01, *(uint32_t*)&l23);
        }
        __syncthreads();

        #pragma unroll 2
        for (int kcl = 0; kcl < 8; kcl++) {
            int kcg = chunk * 8 + kcl;
            uint32_t ah[4], al[4];
            LDSM4(ah, aHiBase + kcl * 32);
            LDSM4(al, aLoBase + kcl * 32);
            uint32_t bh[2][4], bl[2][4];
            #pragma unroll
            for (int j = 0; j < 2; j++) {
                LDSM4T(bh[j], bHiBase + kcg * (16 * W_STRIDE_B) + j * 32);
                LDSM4T(bl[j], bLoBase + kcg * (16 * W_STRIDE_B) + j * 32);
            }
            #pragma unroll
            for (int j = 0; j < 2; j++) {
                MMA16816(d[2 * j],     ah, bh[j][0], bh[j][1]);
                MMA16816(d[2 * j],     ah, bl[j][0], bl[j][1]);
                MMA16816(d[2 * j],     al, bh[j][0], bh[j][1]);
                MMA16816(d[2 * j + 1], ah, bh[j][2], bh[j][3]);
                MMA16816(d[2 * j + 1], ah, bl[j][2], bl[j][3]);
                MMA16816(d[2 * j + 1], al, bh[j][2], bh[j][3]);
            }
        }
        __syncthreads();
    }

    // ---- epilogue: write z + fused s_l/s_r ----
    float* slr = (float*)(smem + SM_SLR);
    const int q = lane >> 2, cq = (lane & 3) * 2;
    const int r1 = row0 + m0 + q, r2 = r1 + 8;
    float sl1 = 0.f, sr1 = 0.f, sl2 = 0.f, sr2 = 0.f;
    #pragma unroll
    for (int i = 0; i < 4; i++) {
        int c = wn * 32 + i * 8 + cq;
        float a0 = __ldg(&a_attn[c]),      a1 = __ldg(&a_attn[c + 1]);
        float b0 = __ldg(&a_attn[64 + c]), b1 = __ldg(&a_attn[64 + c + 1]);
        sl1 += d[i][0] * a0 + d[i][1] * a1;
        sr1 += d[i][0] * b0 + d[i][1] * b1;
        sl2 += d[i][2] * a0 + d[i][3] * a1;
        sr2 += d[i][2] * b0 + d[i][3] * b1;
        if (r1 < N_NODES) *(float2*)&g_z[r1 * OUT_DIM + c] = make_float2(d[i][0], d[i][1]);
        if (r2 < N_NODES) *(float2*)&g_z[r2 * OUT_DIM + c] = make_float2(d[i][2], d[i][3]);
    }
    #pragma unroll
    for (int o = 1; o < 4; o <<= 1) {
        sl1 += __shfl_xor_sync(0xffffffffu, sl1, o);
        sr1 += __shfl_xor_sync(0xffffffffu, sr1, o);
        sl2 += __shfl_xor_sync(0xffffffffu, sl2, o);
        sr2 += __shfl_xor_sync(0xffffffffu, sr2, o);
    }
    if ((lane & 3) == 0) {
        *(float2*)&slr[(m0 + q)     * 4 + wn * 2] = make_float2(sl1, sr1);
        *(float2*)&slr[(m0 + q + 8) * 4 + wn * 2] = make_float2(sl2, sr2);
    }
    __syncthreads();
    if (t < TILE_M) {
        int row = row0 + t;
        if (row < N_NODES) {
            g_sl[row] = slr[t * 4 + 0] + slr[t * 4 + 2];
            g_sr[row] = slr[t * 4 + 1] + slr[t * 4 + 3];
        }
    }
}

// ---------------- zero histogram + denominators ----------------
__global__ void zero_kernel() {
    int i = blockIdx.x * blockDim.x + threadIdx.x;
    if (i <= N_NODES) g_off[i] = 0;
    if (i < N_NODES)  g_den[i] = 0.f;
}

// ---------------- histogram (4 edges/thread) ----------------
__global__ void hist_kernel(const int* __restrict__ edge_dst) {
    int i = blockIdx.x * blockDim.x + threadIdx.x;
    if (i * 4 >= N_EDGES) return;
    int4 d = ((const int4*)edge_dst)[i];
    atomicAdd(&g_off[d.x + 1], 1);
    atomicAdd(&g_off[d.y + 1], 1);
    atomicAdd(&g_off[d.z + 1], 1);
    atomicAdd(&g_off[d.w + 1], 1);
}

// ---------------- thread-coarsened single-block scan ----------------
__global__ void scan_kernel() {
    const int C = 49;
    __shared__ int wsum[32];
    const int t = threadIdx.x, lane = t & 31, w = t >> 5;
    const int base = 1 + t * C;
    int s = 0;
    #pragma unroll
    for (int i = 0; i < C; i++) {
        int idx = base + i;
        s += (idx <= N_NODES) ? g_off[idx] : 0;
    }
    int x = s;
    #pragma unroll
    for (int o = 1; o < 32; o <<= 1) {
        int y = __shfl_up_sync(0xffffffffu, x, o);
        if (lane >= o) x += y;
    }
    if (lane == 31) wsum[w] = x;
    __syncthreads();
    if (w == 0) {
        int v = wsum[lane];
        #pragma unroll
        for (int o = 1; o < 32; o <<= 1) {
            int y = __shfl_up_sync(0xffffffffu, v, o);
            if (lane >= o) v += y;
        }
        wsum[lane] = v;
    }
    __syncthreads();
    int run = x - s + ((w > 0) ? wsum[w - 1] : 0);
    #pragma unroll
    for (int i = 0; i < C; i++) {
        int idx = base + i;
        if (idx <= N_NODES) {
            int cnt = g_off[idx];
            g_cur[idx - 1] = run;
            run += cnt;
            g_off[idx] = run;
        }
    }
}

// ---------------- scatter: 4 edges/thread, packed exp(e)|src + den atomics ----------------
__global__ void scatter_kernel(const int* __restrict__ edge_src,
                               const int* __restrict__ edge_dst) {
    int i = blockIdx.x * blockDim.x + threadIdx.x;
    if (i * 4 >= N_EDGES) return;
    int4 s4 = ((const int4*)edge_src)[i];
    int4 d4 = ((const int4*)edge_dst)[i];
    float e0 = g_sl[s4.x] + g_sr[d4.x];
    float e1 = g_sl[s4.y] + g_sr[d4.y];
    float e2 = g_sl[s4.z] + g_sr[d4.z];
    float e3 = g_sl[s4.w] + g_sr[d4.w];
    e0 = (e0 > 0.f) ? e0 : NEG_SLOPE * e0;
    e1 = (e1 > 0.f) ? e1 : NEG_SLOPE * e1;
    e2 = (e2 > 0.f) ? e2 : NEG_SLOPE * e2;
    e3 = (e3 > 0.f) ? e3 : NEG_SLOPE * e3;
    float x0 = __expf(e0), x1 = __expf(e1), x2 = __expf(e2), x3 = __expf(e3);
    int p0 = atomicAdd(&g_cur[d4.x], 1);
    int p1 = atomicAdd(&g_cur[d4.y], 1);
    int p2 = atomicAdd(&g_cur[d4.z], 1);
    int p3 = atomicAdd(&g_cur[d4.w], 1);
    g_ep[p0] = ((ull)__float_as_uint(x0) << 32) | (unsigned)s4.x;
    g_ep[p1] = ((ull)__float_as_uint(x1) << 32) | (unsigned)s4.y;
    g_ep[p2] = ((ull)__float_as_uint(x2) << 32) | (unsigned)s4.z;
    g_ep[p3] = ((ull)__float_as_uint(x3) << 32) | (unsigned)s4.w;
    atomicAdd(&g_den[d4.x], x0);
    atomicAdd(&g_den[d4.y], x1);
    atomicAdd(&g_den[d4.z], x2);
    atomicAdd(&g_den[d4.w], x3);
}

// ---------------- node phase: TWO nodes per warp (16-lane groups, float4) ----------------
__global__ void node_kernel(float* __restrict__ out) {
    int gt   = blockIdx.x * blockDim.x + threadIdx.x;
    int gw   = gt >> 4;                 // one node per 16-lane group
    int lane = threadIdx.x & 15;        // lane within the half-warp
    if (gw >= N_NODES) return;
    int beg = g_off[gw];
    int end = g_off[gw + 1];

    float4 acc = make_float4(0.f, 0.f, 0.f, 0.f);
    if (beg < end) {
        float invden = 1.0f / g_den[gw];
        int j = beg;
        for (; j + 1 < end; j += 2) {
            ull v0 = g_ep[j], v1 = g_ep[j + 1];
            int s0 = (int)(v0 & 0xffffffffu), s1 = (int)(v1 & 0xffffffffu);
            float4 z0 = *(const float4*)&g_z[s0 * OUT_DIM + 4 * lane];
            float4 z1 = *(const float4*)&g_z[s1 * OUT_DIM + 4 * lane];
            float a0 = __uint_as_float((uint32_t)(v0 >> 32)) * invden;
            float a1 = __uint_as_float((uint32_t)(v1 >> 32)) * invden;
            acc.x += a0 * z0.x + a1 * z1.x;
            acc.y += a0 * z0.y + a1 * z1.y;
            acc.z += a0 * z0.z + a1 * z1.z;
            acc.w += a0 * z0.w + a1 * z1.w;
        }
        if (j < end) {
            ull v0 = g_ep[j];
            int s0 = (int)(v0 & 0xffffffffu);
            float a0 = __uint_as_float((uint32_t)(v0 >> 32)) * invden;
            float4 z0 = *(const float4*)&g_z[s0 * OUT_DIM + 4 * lane];
            acc.x += a0 * z0.x;
            acc.y += a0 * z0.y;
            acc.z += a0 * z0.z;
            acc.w += a0 * z0.w;
        }
    }
    *(float4*)&out[gw * OUT_DIM + 4 * lane] = acc;
}

// ---------------- launch: fork-join two streams inside capture ----------------
extern "C" void kernel_launch(void* const* d_in, const int* in_sizes, int n_in,
                              void* d_out, int out_size) {
    const float* h        = (const float*)d_in[0];
    const int*   edge_src = (const int*)d_in[1];
    const int*   edge_dst = (const int*)d_in[2];
    const float* W_fc     = (const float*)d_in[3];
    const float* a_attn   = (const float*)d_in[4];
    float* out = (float*)d_out;

    static cudaStream_t sB = nullptr;
    static cudaEvent_t  evFork = nullptr, evJoin = nullptr;
    if (!sB) {
        cudaStreamCreateWithFlags(&sB, cudaStreamNonBlocking);
        cudaEventCreateWithFlags(&evFork, cudaEventDisableTiming);
        cudaEventCreateWithFlags(&evJoin, cudaEventDisableTiming);
        cudaFuncSetAttribute(gemm_kernel, cudaFuncAttributeMaxDynamicSharedMemorySize, SM_TOTAL);
    }

    // fork: stream B handles the edge-dst-only CSR build
    cudaEventRecord(evFork, 0);
    cudaStreamWaitEvent(sB, evFork, 0);

    zero_kernel<<<(N_NODES + 256) / 256, 256, 0, sB>>>();
    hist_kernel<<<(N_EDGES / 4 + 255) / 256, 256, 0, sB>>>(edge_dst);
    scan_kernel<<<1, 1024, 0, sB>>>();
    cudaEventRecord(evJoin, sB);

    // main stream: gemm (W convert inlined) with fused s_l/s_r
    gemm_kernel<<<(N_NODES + TILE_M - 1) / TILE_M, 256, SM_TOTAL>>>(h, W_fc, a_attn);

    // join, then the dependent tail
    cudaStreamWaitEvent(0, evJoin, 0);
    scatter_kernel<<<(N_EDGES / 4 + 255) / 256, 256>>>(edge_src, edge_dst);
    node_kernel<<<(N_NODES * 16 + 255) / 256, 256>>>(out);
}

// round 14
// speedup vs baseline: 1.1797x; 1.0235x over previous
#include <cuda_runtime.h>
#include <cuda_bf16.h>
#include <cstdint>

#define N_NODES 50000
#define N_EDGES 800000
#define IN_DIM  256
#define OUT_DIM 64
#define NEG_SLOPE 0.01f
#define TILE_M 64

typedef unsigned long long ull;

// ---------------- device scratch ----------------
__device__ float g_z[N_NODES * OUT_DIM];     // 12.8 MB, L2-resident
__device__ float g_sl[N_NODES];
__device__ float g_sr[N_NODES];
__device__ float g_den[N_NODES];
__device__ int   g_off[N_NODES + 1];
__device__ int   g_cur[N_NODES];
__device__ ull   g_ep[N_EDGES];              // packed (exp(e)<<32 | src), dst-sorted

__device__ __forceinline__ uint32_t smem_u32(const void* p) {
    uint32_t a;
    asm("{ .reg .u64 t; cvta.to.shared.u64 t, %1; cvt.u32.u64 %0, t; }" : "=r"(a) : "l"(p));
    return a;
}

#define LDSM4(R, addr) \
    asm volatile("ldmatrix.sync.aligned.m8n8.x4.shared.b16 {%0,%1,%2,%3}, [%4];" \
        : "=r"((R)[0]), "=r"((R)[1]), "=r"((R)[2]), "=r"((R)[3]) : "r"(addr))
#define LDSM4T(R, addr) \
    asm volatile("ldmatrix.sync.aligned.m8n8.x4.trans.shared.b16 {%0,%1,%2,%3}, [%4];" \
        : "=r"((R)[0]), "=r"((R)[1]), "=r"((R)[2]), "=r"((R)[3]) : "r"(addr))
#define MMA16816(D, A, b0, b1) \
    asm volatile("mma.sync.aligned.m16n8k16.row.col.f32.bf16.bf16.f32 " \
        "{%0,%1,%2,%3}, {%4,%5,%6,%7}, {%8,%9}, {%0,%1,%2,%3};" \
        : "+f"((D)[0]), "+f"((D)[1]), "+f"((D)[2]), "+f"((D)[3]) \
        : "r"((A)[0]), "r"((A)[1]), "r"((A)[2]), "r"((A)[3]), "r"(b0), "r"(b1))

// ---------------- SMEM layout (bytes) ----------------
#define W_STRIDE_B 144
#define A_STRIDE_B 272
#define SM_WHI   0
#define SM_WLO   36864
#define SM_AHI   73728
#define SM_ALO   91136
#define SM_SLR   108544
#define SM_TOTAL 109568

// ---------------- GEMM: mma.sync bf16x3, 2 CTA/SM, inline W convert (MEASURED 41.8us) ----------------
__global__ void __launch_bounds__(256, 2) gemm_kernel(const float* __restrict__ h,
                                                      const float* __restrict__ W,
                                                      const float* __restrict__ a_attn) {
    extern __shared__ char smem[];
    const uint32_t sb = smem_u32(smem);
    const int t = threadIdx.x, wid = t >> 5, lane = t & 31;
    const int row0 = blockIdx.x * TILE_M;

    // ---- convert W fp32 -> bf16 hi/lo into padded smem ----
    for (int i = t; i < IN_DIM * OUT_DIM; i += 256) {
        int k = i >> 6, n = i & 63;
        float w = W[i];
        __nv_bfloat16 wh = __float2bfloat16(w);
        __nv_bfloat16 wl = __float2bfloat16(w - __bfloat162float(wh));
        *(__nv_bfloat16*)(smem + SM_WHI + k * W_STRIDE_B + n * 2) = wh;
        *(__nv_bfloat16*)(smem + SM_WLO + k * W_STRIDE_B + n * 2) = wl;
    }

    const int wm = wid & 3, wn = wid >> 2;
    const int m0 = wm * 16;
    const int lr = lane & 7, lh = (lane >> 3) & 1, lq = lane >> 4;

    const uint32_t aHiBase = sb + SM_AHI + (uint32_t)(m0 + lr + lh * 8) * A_STRIDE_B + lq * 16;
    const uint32_t aLoBase = aHiBase + (SM_ALO - SM_AHI);
    const uint32_t bHiBase = sb + SM_WHI + (uint32_t)(lr + lh * 8) * W_STRIDE_B + wn * 64 + lq * 16;
    const uint32_t bLoBase = bHiBase + (SM_WLO - SM_WHI);

    float d[4][4];
    #pragma unroll
    for (int i = 0; i < 4; i++)
        #pragma unroll
        for (int j = 0; j < 4; j++) d[i][j] = 0.f;

    #pragma unroll 1
    for (int chunk = 0; chunk < 2; chunk++) {
        #pragma unroll
        for (int i = t; i < TILE_M * 32; i += 256) {
            int r = i >> 5, k4 = i & 31;
            int gr = row0 + r;
            float4 v = (gr < N_NODES)
                     ? ((const float4*)h)[gr * (IN_DIM / 4) + chunk * 32 + k4]
                     : make_float4(0.f, 0.f, 0.f, 0.f);
            __nv_bfloat162 h01 = __floats2bfloat162_rn(v.x, v.y);
            __nv_bfloat162 h23 = __floats2bfloat162_rn(v.z, v.w);
            __nv_bfloat162 l01 = __floats2bfloat162_rn(v.x - __bfloat162float(h01.x),
                                                       v.y - __bfloat162float(h01.y));
            __nv_bfloat162 l23 = __floats2bfloat162_rn(v.z - __bfloat162float(h23.x),
                                                       v.w - __bfloat162float(h23.y));
            uint32_t off = (uint32_t)r * A_STRIDE_B + k4 * 8;
            *(uint2*)(smem + SM_AHI + off) = make_uint2(*(uint32_t*)&h01, *(uint32_t*)&h23);
            *(uint2*)(smem + SM_ALO + off) = make_uint2(*(uint32_t*)&l01, *(uint32_t*)&l23);
        }
        __syncthreads();

        #pragma unroll 2
        for (int kcl = 0; kcl < 8; kcl++) {
            int kcg = chunk * 8 + kcl;
            uint32_t ah[4], al[4];
            LDSM4(ah, aHiBase + kcl * 32);
            LDSM4(al, aLoBase + kcl * 32);
            uint32_t bh[2][4], bl[2][4];
            #pragma unroll
            for (int j = 0; j < 2; j++) {
                LDSM4T(bh[j], bHiBase + kcg * (16 * W_STRIDE_B) + j * 32);
                LDSM4T(bl[j], bLoBase + kcg * (16 * W_STRIDE_B) + j * 32);
            }
            #pragma unroll
            for (int j = 0; j < 2; j++) {
                MMA16816(d[2 * j],     ah, bh[j][0], bh[j][1]);
                MMA16816(d[2 * j],     ah, bl[j][0], bl[j][1]);
                MMA16816(d[2 * j],     al, bh[j][0], bh[j][1]);
                MMA16816(d[2 * j + 1], ah, bh[j][2], bh[j][3]);
                MMA16816(d[2 * j + 1], ah, bl[j][2], bl[j][3]);
                MMA16816(d[2 * j + 1], al, bh[j][2], bh[j][3]);
            }
        }
        __syncthreads();
    }

    // ---- epilogue: write z + fused s_l/s_r ----
    float* slr = (float*)(smem + SM_SLR);
    const int q = lane >> 2, cq = (lane & 3) * 2;
    const int r1 = row0 + m0 + q, r2 = r1 + 8;
    float sl1 = 0.f, sr1 = 0.f, sl2 = 0.f, sr2 = 0.f;
    #pragma unroll
    for (int i = 0; i < 4; i++) {
        int c = wn * 32 + i * 8 + cq;
        float a0 = __ldg(&a_attn[c]),      a1 = __ldg(&a_attn[c + 1]);
        float b0 = __ldg(&a_attn[64 + c]), b1 = __ldg(&a_attn[64 + c + 1]);
        sl1 += d[i][0] * a0 + d[i][1] * a1;
        sr1 += d[i][0] * b0 + d[i][1] * b1;
        sl2 += d[i][2] * a0 + d[i][3] * a1;
        sr2 += d[i][2] * b0 + d[i][3] * b1;
        if (r1 < N_NODES) *(float2*)&g_z[r1 * OUT_DIM + c] = make_float2(d[i][0], d[i][1]);
        if (r2 < N_NODES) *(float2*)&g_z[r2 * OUT_DIM + c] = make_float2(d[i][2], d[i][3]);
    }
    #pragma unroll
    for (int o = 1; o < 4; o <<= 1) {
        sl1 += __shfl_xor_sync(0xffffffffu, sl1, o);
        sr1 += __shfl_xor_sync(0xffffffffu, sr1, o);
        sl2 += __shfl_xor_sync(0xffffffffu, sl2, o);
        sr2 += __shfl_xor_sync(0xffffffffu, sr2, o);
    }
    if ((lane & 3) == 0) {
        *(float2*)&slr[(m0 + q)     * 4 + wn * 2] = make_float2(sl1, sr1);
        *(float2*)&slr[(m0 + q + 8) * 4 + wn * 2] = make_float2(sl2, sr2);
    }
    __syncthreads();
    if (t < TILE_M) {
        int row = row0 + t;
        if (row < N_NODES) {
            g_sl[row] = slr[t * 4 + 0] + slr[t * 4 + 2];
            g_sr[row] = slr[t * 4 + 1] + slr[t * 4 + 3];
        }
    }
}

// ---------------- zero histogram + denominators ----------------
__global__ void zero_kernel() {
    int i = blockIdx.x * blockDim.x + threadIdx.x;
    if (i <= N_NODES) g_off[i] = 0;
    if (i < N_NODES)  g_den[i] = 0.f;
}

// ---------------- histogram (4 edges/thread) ----------------
__global__ void hist_kernel(const int* __restrict__ edge_dst) {
    int i = blockIdx.x * blockDim.x + threadIdx.x;
    if (i * 4 >= N_EDGES) return;
    int4 d = ((const int4*)edge_dst)[i];
    atomicAdd(&g_off[d.x + 1], 1);
    atomicAdd(&g_off[d.y + 1], 1);
    atomicAdd(&g_off[d.z + 1], 1);
    atomicAdd(&g_off[d.w + 1], 1);
}

// ---------------- thread-coarsened single-block scan ----------------
__global__ void scan_kernel() {
    const int C = 49;
    __shared__ int wsum[32];
    const int t = threadIdx.x, lane = t & 31, w = t >> 5;
    const int base = 1 + t * C;
    int s = 0;
    #pragma unroll
    for (int i = 0; i < C; i++) {
        int idx = base + i;
        s += (idx <= N_NODES) ? g_off[idx] : 0;
    }
    int x = s;
    #pragma unroll
    for (int o = 1; o < 32; o <<= 1) {
        int y = __shfl_up_sync(0xffffffffu, x, o);
        if (lane >= o) x += y;
    }
    if (lane == 31) wsum[w] = x;
    __syncthreads();
    if (w == 0) {
        int v = wsum[lane];
        #pragma unroll
        for (int o = 1; o < 32; o <<= 1) {
            int y = __shfl_up_sync(0xffffffffu, v, o);
            if (lane >= o) v += y;
        }
        wsum[lane] = v;
    }
    __syncthreads();
    int run = x - s + ((w > 0) ? wsum[w - 1] : 0);
    #pragma unroll
    for (int i = 0; i < C; i++) {
        int idx = base + i;
        if (idx <= N_NODES) {
            int cnt = g_off[idx];
            g_cur[idx - 1] = run;
            run += cnt;
            g_off[idx] = run;
        }
    }
}

// ---------------- scatter: 4 edges/thread, packed exp(e)|src + den atomics ----------------
__global__ void scatter_kernel(const int* __restrict__ edge_src,
                               const int* __restrict__ edge_dst) {
    int i = blockIdx.x * blockDim.x + threadIdx.x;
    if (i * 4 >= N_EDGES) return;
    int4 s4 = ((const int4*)edge_src)[i];
    int4 d4 = ((const int4*)edge_dst)[i];
    float e0 = g_sl[s4.x] + g_sr[d4.x];
    float e1 = g_sl[s4.y] + g_sr[d4.y];
    float e2 = g_sl[s4.z] + g_sr[d4.z];
    float e3 = g_sl[s4.w] + g_sr[d4.w];
    e0 = (e0 > 0.f) ? e0 : NEG_SLOPE * e0;
    e1 = (e1 > 0.f) ? e1 : NEG_SLOPE * e1;
    e2 = (e2 > 0.f) ? e2 : NEG_SLOPE * e2;
    e3 = (e3 > 0.f) ? e3 : NEG_SLOPE * e3;
    float x0 = __expf(e0), x1 = __expf(e1), x2 = __expf(e2), x3 = __expf(e3);
    int p0 = atomicAdd(&g_cur[d4.x], 1);
    int p1 = atomicAdd(&g_cur[d4.y], 1);
    int p2 = atomicAdd(&g_cur[d4.z], 1);
    int p3 = atomicAdd(&g_cur[d4.w], 1);
    g_ep[p0] = ((ull)__float_as_uint(x0) << 32) | (unsigned)s4.x;
    g_ep[p1] = ((ull)__float_as_uint(x1) << 32) | (unsigned)s4.y;
    g_ep[p2] = ((ull)__float_as_uint(x2) << 32) | (unsigned)s4.z;
    g_ep[p3] = ((ull)__float_as_uint(x3) << 32) | (unsigned)s4.w;
    atomicAdd(&g_den[d4.x], x0);
    atomicAdd(&g_den[d4.y], x1);
    atomicAdd(&g_den[d4.z], x2);
    atomicAdd(&g_den[d4.w], x3);
}

// ---------------- node phase: one warp per dst, single pass, unroll 4 (PROVEN 124.4us) ----------------
__global__ void node_kernel(float* __restrict__ out) {
    int gw   = (blockIdx.x * blockDim.x + threadIdx.x) >> 5;
    int lane = threadIdx.x & 31;
    if (gw >= N_NODES) return;
    int beg = g_off[gw];
    int end = g_off[gw + 1];

    float2 acc = make_float2(0.f, 0.f);
    if (beg < end) {
        float invden = 1.0f / g_den[gw];
        int j = beg;
        for (; j + 3 < end; j += 4) {
            ull v0 = g_ep[j],     v1 = g_ep[j + 1];
            ull v2 = g_ep[j + 2], v3 = g_ep[j + 3];
            int s0 = (int)(v0 & 0xffffffffu), s1 = (int)(v1 & 0xffffffffu);
            int s2 = (int)(v2 & 0xffffffffu), s3 = (int)(v3 & 0xffffffffu);
            float2 z0 = *(const float2*)&g_z[s0 * OUT_DIM + 2 * lane];
            float2 z1 = *(const float2*)&g_z[s1 * OUT_DIM + 2 * lane];
            float2 z2 = *(const float2*)&g_z[s2 * OUT_DIM + 2 * lane];
            float2 z3 = *(const float2*)&g_z[s3 * OUT_DIM + 2 * lane];
            float a0 = __uint_as_float((uint32_t)(v0 >> 32)) * invden;
            float a1 = __uint_as_float((uint32_t)(v1 >> 32)) * invden;
            float a2 = __uint_as_float((uint32_t)(v2 >> 32)) * invden;
            float a3 = __uint_as_float((uint32_t)(v3 >> 32)) * invden;
            acc.x += a0 * z0.x + a1 * z1.x + a2 * z2.x + a3 * z3.x;
            acc.y += a0 * z0.y + a1 * z1.y + a2 * z2.y + a3 * z3.y;
        }
        for (; j < end; ++j) {
            ull v0 = g_ep[j];
            int s0 = (int)(v0 & 0xffffffffu);
            float a0 = __uint_as_float((uint32_t)(v0 >> 32)) * invden;
            float2 z0 = *(const float2*)&g_z[s0 * OUT_DIM + 2 * lane];
            acc.x += a0 * z0.x;
            acc.y += a0 * z0.y;
        }
    }
    *(float2*)&out[gw * OUT_DIM + 2 * lane] = acc;
}

// ---------------- launch: fork-join two streams inside capture ----------------
extern "C" void kernel_launch(void* const* d_in, const int* in_sizes, int n_in,
                              void* d_out, int out_size) {
    const float* h        = (const float*)d_in[0];
    const int*   edge_src = (const int*)d_in[1];
    const int*   edge_dst = (const int*)d_in[2];
    const float* W_fc     = (const float*)d_in[3];
    const float* a_attn   = (const float*)d_in[4];
    float* out = (float*)d_out;

    static cudaStream_t sB = nullptr;
    static cudaEvent_t  evFork = nullptr, evJoin = nullptr;
    if (!sB) {
        cudaStreamCreateWithFlags(&sB, cudaStreamNonBlocking);
        cudaEventCreateWithFlags(&evFork, cudaEventDisableTiming);
        cudaEventCreateWithFlags(&evJoin, cudaEventDisableTiming);
        cudaFuncSetAttribute(gemm_kernel, cudaFuncAttributeMaxDynamicSharedMemorySize, SM_TOTAL);
    }

    // fork: stream B handles the edge-dst-only CSR build
    cudaEventRecord(evFork, 0);
    cudaStreamWaitEvent(sB, evFork, 0);

    zero_kernel<<<(N_NODES + 256) / 256, 256, 0, sB>>>();
    hist_kernel<<<(N_EDGES / 4 + 255) / 256, 256, 0, sB>>>(edge_dst);
    scan_kernel<<<1, 1024, 0, sB>>>();
    cudaEventRecord(evJoin, sB);

    // main stream: gemm (W convert inlined) with fused s_l/s_r
    gemm_kernel<<<(N_NODES + TILE_M - 1) / TILE_M, 256, SM_TOTAL>>>(h, W_fc, a_attn);

    // join, then the dependent tail
    cudaStreamWaitEvent(0, evJoin, 0);
    scatter_kernel<<<(N_EDGES / 4 + 255) / 256, 256>>>(edge_src, edge_dst);
    node_kernel<<<(N_NODES * 32 + 255) / 256, 256>>>(out);
}

// round 15
// speedup vs baseline: 2.4639x; 2.0886x over previous
#include <cuda_runtime.h>
#include <cuda_bf16.h>
#include <cstdint>

#define N_NODES 50000
#define N_EDGES 800000
#define IN_DIM  256
#define OUT_DIM 64
#define NEG_SLOPE 0.01f
#define TILE_M 64

typedef unsigned long long ull;

// ---------------- device scratch ----------------
__device__ float g_z[N_NODES * OUT_DIM];     // 12.8 MB, L2-resident
__device__ float g_sl[N_NODES];
__device__ float g_sr[N_NODES];
__device__ float g_den[N_NODES];
__device__ int   g_off[N_NODES + 1];
__device__ int   g_cur[N_NODES];
__device__ ull   g_ep[N_EDGES];
__device__ __nv_bfloat16 g_wh[IN_DIM * OUT_DIM];   // W hi (bf16), row-major [k][n]
__device__ __nv_bfloat16 g_wl[IN_DIM * OUT_DIM];   // W lo

__device__ __forceinline__ uint32_t smem_u32(const void* p) {
    uint32_t a;
    asm("{ .reg .u64 t; cvta.to.shared.u64 t, %1; cvt.u32.u64 %0, t; }" : "=r"(a) : "l"(p));
    return a;
}

#define LDSM4(R, addr) \
    asm volatile("ldmatrix.sync.aligned.m8n8.x4.shared.b16 {%0,%1,%2,%3}, [%4];" \
        : "=r"((R)[0]), "=r"((R)[1]), "=r"((R)[2]), "=r"((R)[3]) : "r"(addr))
#define LDSM4T(R, addr) \
    asm volatile("ldmatrix.sync.aligned.m8n8.x4.trans.shared.b16 {%0,%1,%2,%3}, [%4];" \
        : "=r"((R)[0]), "=r"((R)[1]), "=r"((R)[2]), "=r"((R)[3]) : "r"(addr))
#define MMA16816(D, A, b0, b1) \
    asm volatile("mma.sync.aligned.m16n8k16.row.col.f32.bf16.bf16.f32 " \
        "{%0,%1,%2,%3}, {%4,%5,%6,%7}, {%8,%9}, {%0,%1,%2,%3};" \
        : "+f"((D)[0]), "+f"((D)[1]), "+f"((D)[2]), "+f"((D)[3]) \
        : "r"((A)[0]), "r"((A)[1]), "r"((A)[2]), "r"((A)[3]), "r"(b0), "r"(b1))

// ---------------- SMEM layout (bytes) ----------------
#define W_STRIDE_B 144
#define A_STRIDE_B 272
#define SM_WHI   0
#define SM_WLO   36864
#define SM_AHI   73728
#define SM_ALO   91136
#define SM_SLR   108544
#define SM_TOTAL 109568

// ---------------- W prep: fp32 -> bf16 hi/lo (once, to global) ----------------
__global__ void wprep_kernel(const float* __restrict__ W) {
    int i = blockIdx.x * blockDim.x + threadIdx.x;
    if (i >= IN_DIM * OUT_DIM) return;
    float w = W[i];
    __nv_bfloat16 wh = __float2bfloat16(w);
    __nv_bfloat16 wl = __float2bfloat16(w - __bfloat162float(wh));
    g_wh[i] = wh;
    g_wl[i] = wl;
}

// ---------------- GEMM: z = h @ W via mma.sync bf16x3, 2 CTA/SM ----------------
// 256 threads = 8 warps: warp = (m-tile wid&3) x (n-half wid>>2).
// TILE_M=64 rows/CTA, K in 2 chunks of 128 (A smem single-buffered per chunk).
__global__ void __launch_bounds__(256, 2) gemm_kernel(const float* __restrict__ h,
                                                      const float* __restrict__ a_attn) {
    extern __shared__ char smem[];
    const uint32_t sb = smem_u32(smem);
    const int t = threadIdx.x, wid = t >> 5, lane = t & 31;
    const int row0 = blockIdx.x * TILE_M;

    // ---- copy precomputed W hi/lo (bf16) into padded smem ----
    for (int i = t; i < 2048; i += 256) {           // 2048 uint4 = 32KB per matrix
        int r = i >> 3, u = i & 7;
        uint32_t off = (uint32_t)r * W_STRIDE_B + u * 16;
        *(uint4*)(smem + SM_WHI + off) = ((const uint4*)g_wh)[i];
        *(uint4*)(smem + SM_WLO + off) = ((const uint4*)g_wl)[i];
    }

    const int wm = wid & 3, wn = wid >> 2;
    const int m0 = wm * 16;
    const int lr = lane & 7, lh = (lane >> 3) & 1, lq = lane >> 4;

    const uint32_t aHiBase = sb + SM_AHI + (uint32_t)(m0 + lr + lh * 8) * A_STRIDE_B + lq * 16;
    const uint32_t aLoBase = aHiBase + (SM_ALO - SM_AHI);
    const uint32_t bHiBase = sb + SM_WHI + (uint32_t)(lr + lh * 8) * W_STRIDE_B + wn * 64 + lq * 16;
    const uint32_t bLoBase = bHiBase + (SM_WLO - SM_WHI);

    float d[4][4];
    #pragma unroll
    for (int i = 0; i < 4; i++)
        #pragma unroll
        for (int j = 0; j < 4; j++) d[i][j] = 0.f;

    #pragma unroll 1
    for (int chunk = 0; chunk < 2; chunk++) {
        // load A chunk: 64 rows x 128 cols fp32 -> bf16 hi/lo
        #pragma unroll
        for (int i = t; i < TILE_M * 32; i += 256) {
            int r = i >> 5, k4 = i & 31;
            int gr = row0 + r;
            float4 v = (gr < N_NODES)
                     ? ((const float4*)h)[gr * (IN_DIM / 4) + chunk * 32 + k4]
                     : make_float4(0.f, 0.f, 0.f, 0.f);
            __nv_bfloat162 h01 = __floats2bfloat162_rn(v.x, v.y);
            __nv_bfloat162 h23 = __floats2bfloat162_rn(v.z, v.w);
            __nv_bfloat162 l01 = __floats2bfloat162_rn(v.x - __bfloat162float(h01.x),
                                                       v.y - __bfloat162float(h01.y));
            __nv_bfloat162 l23 = __floats2bfloat162_rn(v.z - __bfloat162float(h23.x),
                                                       v.w - __bfloat162float(h23.y));
            uint32_t off = (uint32_t)r * A_STRIDE_B + k4 * 8;
            *(uint2*)(smem + SM_AHI + off) = make_uint2(*(uint32_t*)&h01, *(uint32_t*)&h23);
            *(uint2*)(smem + SM_ALO + off) = make_uint2(*(uint32_t*)&l01, *(uint32_t*)&l23);
        }
        __syncthreads();

        #pragma unroll 2
        for (int kcl = 0; kcl < 8; kcl++) {
            int kcg = chunk * 8 + kcl;
            uint32_t ah[4], al[4];
            LDSM4(ah, aHiBase + kcl * 32);
            LDSM4(al, aLoBase + kcl * 32);
            uint32_t bh[2][4], bl[2][4];
            #pragma unroll
            for (int j = 0; j < 2; j++) {
                LDSM4T(bh[j], bHiBase + kcg * (16 * W_STRIDE_B) + j * 32);
                LDSM4T(bl[j], bLoBase + kcg * (16 * W_STRIDE_B) + j * 32);
            }
            #pragma unroll
            for (int j = 0; j < 2; j++) {
                MMA16816(d[2 * j],     ah, bh[j][0], bh[j][1]);
                MMA16816(d[2 * j],     ah, bl[j][0], bl[j][1]);
                MMA16816(d[2 * j],     al, bh[j][0], bh[j][1]);
                MMA16816(d[2 * j + 1], ah, bh[j][2], bh[j][3]);
                MMA16816(d[2 * j + 1], ah, bl[j][2], bl[j][3]);
                MMA16816(d[2 * j + 1], al, bh[j][2], bh[j][3]);
            }
        }
        __syncthreads();   // before next chunk overwrites A
    }

    // ---- epilogue: write z + fused s_l/s_r ----
    float* slr = (float*)(smem + SM_SLR);   // [64][2 halves][2]
    const int q = lane >> 2, cq = (lane & 3) * 2;
    const int r1 = row0 + m0 + q, r2 = r1 + 8;
    float sl1 = 0.f, sr1 = 0.f, sl2 = 0.f, sr2 = 0.f;
    #pragma unroll
    for (int i = 0; i < 4; i++) {
        int c = wn * 32 + i * 8 + cq;
        float a0 = __ldg(&a_attn[c]),      a1 = __ldg(&a_attn[c + 1]);
        float b0 = __ldg(&a_attn[64 + c]), b1 = __ldg(&a_attn[64 + c + 1]);
        sl1 += d[i][0] * a0 + d[i][1] * a1;
        sr1 += d[i][0] * b0 + d[i][1] * b1;
        sl2 += d[i][2] * a0 + d[i][3] * a1;
        sr2 += d[i][2] * b0 + d[i][3] * b1;
        if (r1 < N_NODES) *(float2*)&g_z[r1 * OUT_DIM + c] = make_float2(d[i][0], d[i][1]);
        if (r2 < N_NODES) *(float2*)&g_z[r2 * OUT_DIM + c] = make_float2(d[i][2], d[i][3]);
    }
    #pragma unroll
    for (int o = 1; o < 4; o <<= 1) {
        sl1 += __shfl_xor_sync(0xffffffffu, sl1, o);
        sr1 += __shfl_xor_sync(0xffffffffu, sr1, o);
        sl2 += __shfl_xor_sync(0xffffffffu, sl2, o);
        sr2 += __shfl_xor_sync(0xffffffffu, sr2, o);
    }
    if ((lane & 3) == 0) {
        *(float2*)&slr[(m0 + q)     * 4 + wn * 2] = make_float2(sl1, sr1);
        *(float2*)&slr[(m0 + q + 8) * 4 + wn * 2] = make_float2(sl2, sr2);
    }
    __syncthreads();
    if (t < TILE_M) {
        int row = row0 + t;
        if (row < N_NODES) {
            g_sl[row] = slr[t * 4 + 0] + slr[t * 4 + 2];
            g_sr[row] = slr[t * 4 + 1] + slr[t * 4 + 3];
        }
    }
}

// ---------------- zero histogram + denominators ----------------
__global__ void zero_kernel() {
    int i = blockIdx.x * blockDim.x + threadIdx.x;
    if (i <= N_NODES) g_off[i] = 0;
    if (i < N_NODES)  g_den[i] = 0.f;
}

// ---------------- histogram (4 edges/thread) ----------------
__global__ void hist_kernel(const int* __restrict__ edge_dst) {
    int i = blockIdx.x * blockDim.x + threadIdx.x;
    if (i * 4 >= N_EDGES) return;
    int4 d = ((const int4*)edge_dst)[i];
    atomicAdd(&g_off[d.x + 1], 1);
    atomicAdd(&g_off[d.y + 1], 1);
    atomicAdd(&g_off[d.z + 1], 1);
    atomicAdd(&g_off[d.w + 1], 1);
}

// ---------------- thread-coarsened single-block scan ----------------
__global__ void scan_kernel() {
    const int C = 49;
    __shared__ int wsum[32];
    const int t = threadIdx.x, lane = t & 31, w = t >> 5;
    const int base = 1 + t * C;
    int s = 0;
    #pragma unroll
    for (int i = 0; i < C; i++) {
        int idx = base + i;
        s += (idx <= N_NODES) ? g_off[idx] : 0;
    }
    int x = s;
    #pragma unroll
    for (int o = 1; o < 32; o <<= 1) {
        int y = __shfl_up_sync(0xffffffffu, x, o);
        if (lane >= o) x += y;
    }
    if (lane == 31) wsum[w] = x;
    __syncthreads();
    if (w == 0) {
        int v = wsum[lane];
        #pragma unroll
        for (int o = 1; o < 32; o <<= 1) {
            int y = __shfl_up_sync(0xffffffffu, v, o);
            if (lane >= o) v += y;
        }
        wsum[lane] = v;
    }
    __syncthreads();
    int run = x - s + ((w > 0) ? wsum[w - 1] : 0);
    #pragma unroll
    for (int i = 0; i < C; i++) {
        int idx = base + i;
        if (idx <= N_NODES) {
            int cnt = g_off[idx];
            g_cur[idx - 1] = run;
            run += cnt;
            g_off[idx] = run;
        }
    }
}

// ---------------- scatter: 4 edges/thread, packed exp(e)|src + den atomics ----------------
__global__ void scatter_kernel(const int* __restrict__ edge_src,
                               const int* __restrict__ edge_dst) {
    int i = blockIdx.x * blockDim.x + threadIdx.x;
    if (i * 4 >= N_EDGES) return;
    int4 s4 = ((const int4*)edge_src)[i];
    int4 d4 = ((const int4*)edge_dst)[i];
    float e0 = g_sl[s4.x] + g_sr[d4.x];
    float e1 = g_sl[s4.y] + g_sr[d4.y];
    float e2 = g_sl[s4.z] + g_sr[d4.z];
    float e3 = g_sl[s4.w] + g_sr[d4.w];
    e0 = (e0 > 0.f) ? e0 : NEG_SLOPE * e0;
    e1 = (e1 > 0.f) ? e1 : NEG_SLOPE * e1;
    e2 = (e2 > 0.f) ? e2 : NEG_SLOPE * e2;
    e3 = (e3 > 0.f) ? e3 : NEG_SLOPE * e3;
    float x0 = __expf(e0), x1 = __expf(e1), x2 = __expf(e2), x3 = __expf(e3);
    int p0 = atomicAdd(&g_cur[d4.x], 1);
    int p1 = atomicAdd(&g_cur[d4.y], 1);
    int p2 = atomicAdd(&g_cur[d4.z], 1);
    int p3 = atomicAdd(&g_cur[d4.w], 1);
    g_ep[p0] = ((ull)__float_as_uint(x0) << 32) | (unsigned)s4.x;
    g_ep[p1] = ((ull)__float_as_uint(x1) << 32) | (unsigned)s4.y;
    g_ep[p2] = ((ull)__float_as_uint(x2) << 32) | (unsigned)s4.z;
    g_ep[p3] = ((ull)__float_as_uint(x3) << 32) | (unsigned)s4.w;
    atomicAdd(&g_den[d4.x], x0);
    atomicAdd(&g_den[d4.y], x1);
    atomicAdd(&g_den[d4.z], x2);
    atomicAdd(&g_den[d4.w], x3);
}

// ---------------- node phase: one warp per dst, single pass, unroll 4 ----------------
__global__ void node_kernel(float* __restrict__ out) {
    int gw   = (blockIdx.x * blockDim.x + threadIdx.x) >> 5;
    int lane = threadIdx.x & 31;
    if (gw >= N_NODES) return;
    int beg = g_off[gw];
    int end = g_off[gw + 1];

    float2 acc = make_float2(0.f, 0.f);
    if (beg < end) {
        float invden = 1.0f / g_den[gw];
        int j = beg;
        for (; j + 3 < end; j += 4) {
            ull v0 = g_ep[j],     v1 = g_ep[j + 1];
            ull v2 = g_ep[j + 2], v3 = g_ep[j + 3];
            int s0 = (int)(v0 & 0xffffffffu), s1 = (int)(v1 & 0xffffffffu);
            int s2 = (int)(v2 & 0xffffffffu), s3 = (int)(v3 & 0xffffffffu);
            float2 z0 = *(const float2*)&g_z[s0 * OUT_DIM + 2 * lane];
            float2 z1 = *(const float2*)&g_z[s1 * OUT_DIM + 2 * lane];
            float2 z2 = *(const float2*)&g_z[s2 * OUT_DIM + 2 * lane];
            float2 z3 = *(const float2*)&g_z[s3 * OUT_DIM + 2 * lane];
            float a0 = __uint_as_float((uint32_t)(v0 >> 32)) * invden;
            float a1 = __uint_as_float((uint32_t)(v1 >> 32)) * invden;
            float a2 = __uint_as_float((uint32_t)(v2 >> 32)) * invden;
            float a3 = __uint_as_float((uint32_t)(v3 >> 32)) * invden;
            acc.x += a0 * z0.x + a1 * z1.x + a2 * z2.x + a3 * z3.x;
            acc.y += a0 * z0.y + a1 * z1.y + a2 * z2.y + a3 * z3.y;
        }
        for (; j < end; ++j) {
            ull v0 = g_ep[j];
            int s0 = (int)(v0 & 0xffffffffu);
            float a0 = __uint_as_float((uint32_t)(v0 >> 32)) * invden;
            float2 z0 = *(const float2*)&g_z[s0 * OUT_DIM + 2 * lane];
            acc.x += a0 * z0.x;
            acc.y += a0 * z0.y;
        }
    }
    *(float2*)&out[gw * OUT_DIM + 2 * lane] = acc;
}

// ---------------- launch: fork-join two streams inside capture ----------------
extern "C" void kernel_launch(void* const* d_in, const int* in_sizes, int n_in,
                              void* d_out, int out_size) {
    const float* h        = (const float*)d_in[0];
    const int*   edge_src = (const int*)d_in[1];
    const int*   edge_dst = (const int*)d_in[2];
    const float* W_fc     = (const float*)d_in[3];
    const float* a_attn   = (const float*)d_in[4];
    float* out = (float*)d_out;

    static cudaStream_t sB = nullptr;
    static cudaEvent_t  evFork = nullptr, evJoin = nullptr;
    if (!sB) {
        cudaStreamCreateWithFlags(&sB, cudaStreamNonBlocking);
        cudaEventCreateWithFlags(&evFork, cudaEventDisableTiming);
        cudaEventCreateWithFlags(&evJoin, cudaEventDisableTiming);
        cudaFuncSetAttribute(gemm_kernel, cudaFuncAttributeMaxDynamicSharedMemorySize, SM_TOTAL);
    }

    // fork: stream B handles the edge-dst-only CSR build
    cudaEventRecord(evFork, 0);
    cudaStreamWaitEvent(sB, evFork, 0);

    zero_kernel<<<(N_NODES + 256) / 256, 256, 0, sB>>>();
    hist_kernel<<<(N_EDGES / 4 + 255) / 256, 256, 0, sB>>>(edge_dst);
    scan_kernel<<<1, 1024, 0, sB>>>();
    cudaEventRecord(evJoin, sB);

    // main stream: W prep then gemm with fused s_l/s_r
    wprep_kernel<<<(IN_DIM * OUT_DIM + 255) / 256, 256>>>(W_fc);
    gemm_kernel<<<(N_NODES + TILE_M - 1) / TILE_M, 256, SM_TOTAL>>>(h, a_attn);

    // join, then the dependent tail
    cudaStreamWaitEvent(0, evJoin, 0);
    scatter_kernel<<<(N_EDGES / 4 + 255) / 256, 256>>>(edge_src, edge_dst);
    node_kernel<<<(N_NODES * 32 + 255) / 256, 256>>>(out);
}

// round 16
// speedup vs baseline: 2.4740x; 1.0041x over previous
#include <cuda_runtime.h>
#include <cuda_bf16.h>
#include <cstdint>

#define N_NODES 50000
#define N_EDGES 800000
#define IN_DIM  256
#define OUT_DIM 64
#define NEG_SLOPE 0.01f
#define TILE_M 64

typedef unsigned long long ull;

// ---------------- device scratch ----------------
__device__ float g_z[N_NODES * OUT_DIM];     // 12.8 MB, L2-resident
__device__ float g_sl[N_NODES];
__device__ float g_sr[N_NODES];
__device__ float g_den[N_NODES];
__device__ int   g_off[N_NODES + 1];
__device__ int   g_cur[N_NODES];
__device__ ull   g_ep[N_EDGES];
__device__ __nv_bfloat16 g_wh[IN_DIM * OUT_DIM];   // W hi (bf16), row-major [k][n]
__device__ __nv_bfloat16 g_wl[IN_DIM * OUT_DIM];   // W lo

__device__ __forceinline__ uint32_t smem_u32(const void* p) {
    uint32_t a;
    asm("{ .reg .u64 t; cvta.to.shared.u64 t, %1; cvt.u32.u64 %0, t; }" : "=r"(a) : "l"(p));
    return a;
}

#define LDSM4(R, addr) \
    asm volatile("ldmatrix.sync.aligned.m8n8.x4.shared.b16 {%0,%1,%2,%3}, [%4];" \
        : "=r"((R)[0]), "=r"((R)[1]), "=r"((R)[2]), "=r"((R)[3]) : "r"(addr))
#define LDSM4T(R, addr) \
    asm volatile("ldmatrix.sync.aligned.m8n8.x4.trans.shared.b16 {%0,%1,%2,%3}, [%4];" \
        : "=r"((R)[0]), "=r"((R)[1]), "=r"((R)[2]), "=r"((R)[3]) : "r"(addr))
#define MMA16816(D, A, b0, b1) \
    asm volatile("mma.sync.aligned.m16n8k16.row.col.f32.bf16.bf16.f32 " \
        "{%0,%1,%2,%3}, {%4,%5,%6,%7}, {%8,%9}, {%0,%1,%2,%3};" \
        : "+f"((D)[0]), "+f"((D)[1]), "+f"((D)[2]), "+f"((D)[3]) \
        : "r"((A)[0]), "r"((A)[1]), "r"((A)[2]), "r"((A)[3]), "r"(b0), "r"(b1))

// ---------------- SMEM layout (bytes) ----------------
#define W_STRIDE_B 144
#define A_STRIDE_B 272
#define SM_WHI   0
#define SM_WLO   36864
#define SM_AHI   73728
#define SM_ALO   91136
#define SM_SLR   108544
#define SM_TOTAL 109568

// ---------------- W prep: fp32 -> bf16 hi/lo (once, to global) ----------------
__global__ void wprep_kernel(const float* __restrict__ W) {
    int i = blockIdx.x * blockDim.x + threadIdx.x;
    if (i >= IN_DIM * OUT_DIM) return;
    float w = W[i];
    __nv_bfloat16 wh = __float2bfloat16(w);
    __nv_bfloat16 wl = __float2bfloat16(w - __bfloat162float(wh));
    g_wh[i] = wh;
    g_wl[i] = wl;
}

// ---------------- GEMM: z = h @ W via mma.sync bf16x3, 2 CTA/SM (CHAMPION, DO NOT TOUCH) ----------------
__global__ void __launch_bounds__(256, 2) gemm_kernel(const float* __restrict__ h,
                                                      const float* __restrict__ a_attn) {
    extern __shared__ char smem[];
    const uint32_t sb = smem_u32(smem);
    const int t = threadIdx.x, wid = t >> 5, lane = t & 31;
    const int row0 = blockIdx.x * TILE_M;

    // ---- copy precomputed W hi/lo (bf16) into padded smem ----
    for (int i = t; i < 2048; i += 256) {           // 2048 uint4 = 32KB per matrix
        int r = i >> 3, u = i & 7;
        uint32_t off = (uint32_t)r * W_STRIDE_B + u * 16;
        *(uint4*)(smem + SM_WHI + off) = ((const uint4*)g_wh)[i];
        *(uint4*)(smem + SM_WLO + off) = ((const uint4*)g_wl)[i];
    }

    const int wm = wid & 3, wn = wid >> 2;
    const int m0 = wm * 16;
    const int lr = lane & 7, lh = (lane >> 3) & 1, lq = lane >> 4;

    const uint32_t aHiBase = sb + SM_AHI + (uint32_t)(m0 + lr + lh * 8) * A_STRIDE_B + lq * 16;
    const uint32_t aLoBase = aHiBase + (SM_ALO - SM_AHI);
    const uint32_t bHiBase = sb + SM_WHI + (uint32_t)(lr + lh * 8) * W_STRIDE_B + wn * 64 + lq * 16;
    const uint32_t bLoBase = bHiBase + (SM_WLO - SM_WHI);

    float d[4][4];
    #pragma unroll
    for (int i = 0; i < 4; i++)
        #pragma unroll
        for (int j = 0; j < 4; j++) d[i][j] = 0.f;

    #pragma unroll 1
    for (int chunk = 0; chunk < 2; chunk++) {
        // load A chunk: 64 rows x 128 cols fp32 -> bf16 hi/lo
        #pragma unroll
        for (int i = t; i < TILE_M * 32; i += 256) {
            int r = i >> 5, k4 = i & 31;
            int gr = row0 + r;
            float4 v = (gr < N_NODES)
                     ? ((const float4*)h)[gr * (IN_DIM / 4) + chunk * 32 + k4]
                     : make_float4(0.f, 0.f, 0.f, 0.f);
            __nv_bfloat162 h01 = __floats2bfloat162_rn(v.x, v.y);
            __nv_bfloat162 h23 = __floats2bfloat162_rn(v.z, v.w);
            __nv_bfloat162 l01 = __floats2bfloat162_rn(v.x - __bfloat162float(h01.x),
                                                       v.y - __bfloat162float(h01.y));
            __nv_bfloat162 l23 = __floats2bfloat162_rn(v.z - __bfloat162float(h23.x),
                                                       v.w - __bfloat162float(h23.y));
            uint32_t off = (uint32_t)r * A_STRIDE_B + k4 * 8;
            *(uint2*)(smem + SM_AHI + off) = make_uint2(*(uint32_t*)&h01, *(uint32_t*)&h23);
            *(uint2*)(smem + SM_ALO + off) = make_uint2(*(uint32_t*)&l01, *(uint32_t*)&l23);
        }
        __syncthreads();

        #pragma unroll 2
        for (int kcl = 0; kcl < 8; kcl++) {
            int kcg = chunk * 8 + kcl;
            uint32_t ah[4], al[4];
            LDSM4(ah, aHiBase + kcl * 32);
            LDSM4(al, aLoBase + kcl * 32);
            uint32_t bh[2][4], bl[2][4];
            #pragma unroll
            for (int j = 0; j < 2; j++) {
                LDSM4T(bh[j], bHiBase + kcg * (16 * W_STRIDE_B) + j * 32);
                LDSM4T(bl[j], bLoBase + kcg * (16 * W_STRIDE_B) + j * 32);
            }
            #pragma unroll
            for (int j = 0; j < 2; j++) {
                MMA16816(d[2 * j],     ah, bh[j][0], bh[j][1]);
                MMA16816(d[2 * j],     ah, bl[j][0], bl[j][1]);
                MMA16816(d[2 * j],     al, bh[j][0], bh[j][1]);
                MMA16816(d[2 * j + 1], ah, bh[j][2], bh[j][3]);
                MMA16816(d[2 * j + 1], ah, bl[j][2], bl[j][3]);
                MMA16816(d[2 * j + 1], al, bh[j][2], bh[j][3]);
            }
        }
        __syncthreads();   // before next chunk overwrites A
    }

    // ---- epilogue: write z + fused s_l/s_r ----
    float* slr = (float*)(smem + SM_SLR);   // [64][2 halves][2]
    const int q = lane >> 2, cq = (lane & 3) * 2;
    const int r1 = row0 + m0 + q, r2 = r1 + 8;
    float sl1 = 0.f, sr1 = 0.f, sl2 = 0.f, sr2 = 0.f;
    #pragma unroll
    for (int i = 0; i < 4; i++) {
        int c = wn * 32 + i * 8 + cq;
        float a0 = __ldg(&a_attn[c]),      a1 = __ldg(&a_attn[c + 1]);
        float b0 = __ldg(&a_attn[64 + c]), b1 = __ldg(&a_attn[64 + c + 1]);
        sl1 += d[i][0] * a0 + d[i][1] * a1;
        sr1 += d[i][0] * b0 + d[i][1] * b1;
        sl2 += d[i][2] * a0 + d[i][3] * a1;
        sr2 += d[i][2] * b0 + d[i][3] * b1;
        if (r1 < N_NODES) *(float2*)&g_z[r1 * OUT_DIM + c] = make_float2(d[i][0], d[i][1]);
        if (r2 < N_NODES) *(float2*)&g_z[r2 * OUT_DIM + c] = make_float2(d[i][2], d[i][3]);
    }
    #pragma unroll
    for (int o = 1; o < 4; o <<= 1) {
        sl1 += __shfl_xor_sync(0xffffffffu, sl1, o);
        sr1 += __shfl_xor_sync(0xffffffffu, sr1, o);
        sl2 += __shfl_xor_sync(0xffffffffu, sl2, o);
        sr2 += __shfl_xor_sync(0xffffffffu, sr2, o);
    }
    if ((lane & 3) == 0) {
        *(float2*)&slr[(m0 + q)     * 4 + wn * 2] = make_float2(sl1, sr1);
        *(float2*)&slr[(m0 + q + 8) * 4 + wn * 2] = make_float2(sl2, sr2);
    }
    __syncthreads();
    if (t < TILE_M) {
        int row = row0 + t;
        if (row < N_NODES) {
            g_sl[row] = slr[t * 4 + 0] + slr[t * 4 + 2];
            g_sr[row] = slr[t * 4 + 1] + slr[t * 4 + 3];
        }
    }
}

// ---------------- zero histogram + denominators ----------------
__global__ void zero_kernel() {
    int i = blockIdx.x * blockDim.x + threadIdx.x;
    if (i <= N_NODES) g_off[i] = 0;
    if (i < N_NODES)  g_den[i] = 0.f;
}

// ---------------- histogram (4 edges/thread) ----------------
__global__ void hist_kernel(const int* __restrict__ edge_dst) {
    int i = blockIdx.x * blockDim.x + threadIdx.x;
    if (i * 4 >= N_EDGES) return;
    int4 d = ((const int4*)edge_dst)[i];
    atomicAdd(&g_off[d.x + 1], 1);
    atomicAdd(&g_off[d.y + 1], 1);
    atomicAdd(&g_off[d.z + 1], 1);
    atomicAdd(&g_off[d.w + 1], 1);
}

// ---------------- thread-coarsened single-block scan ----------------
__global__ void scan_kernel() {
    const int C = 49;
    __shared__ int wsum[32];
    const int t = threadIdx.x, lane = t & 31, w = t >> 5;
    const int base = 1 + t * C;
    int s = 0;
    #pragma unroll
    for (int i = 0; i < C; i++) {
        int idx = base + i;
        s += (idx <= N_NODES) ? g_off[idx] : 0;
    }
    int x = s;
    #pragma unroll
    for (int o = 1; o < 32; o <<= 1) {
        int y = __shfl_up_sync(0xffffffffu, x, o);
        if (lane >= o) x += y;
    }
    if (lane == 31) wsum[w] = x;
    __syncthreads();
    if (w == 0) {
        int v = wsum[lane];
        #pragma unroll
        for (int o = 1; o < 32; o <<= 1) {
            int y = __shfl_up_sync(0xffffffffu, v, o);
            if (lane >= o) v += y;
        }
        wsum[lane] = v;
    }
    __syncthreads();
    int run = x - s + ((w > 0) ? wsum[w - 1] : 0);
    #pragma unroll
    for (int i = 0; i < C; i++) {
        int idx = base + i;
        if (idx <= N_NODES) {
            int cnt = g_off[idx];
            g_cur[idx - 1] = run;
            run += cnt;
            g_off[idx] = run;
        }
    }
}

// ---------------- scatter: 8 edges/thread, packed exp(e)|src + den atomics ----------------
__global__ void scatter_kernel(const int* __restrict__ edge_src,
                               const int* __restrict__ edge_dst) {
    int i = blockIdx.x * blockDim.x + threadIdx.x;
    if (i * 8 >= N_EDGES) return;
    int4 sA = ((const int4*)edge_src)[2 * i];
    int4 sB = ((const int4*)edge_src)[2 * i + 1];
    int4 dA = ((const int4*)edge_dst)[2 * i];
    int4 dB = ((const int4*)edge_dst)[2 * i + 1];

    float e0 = g_sl[sA.x] + g_sr[dA.x];
    float e1 = g_sl[sA.y] + g_sr[dA.y];
    float e2 = g_sl[sA.z] + g_sr[dA.z];
    float e3 = g_sl[sA.w] + g_sr[dA.w];
    float e4 = g_sl[sB.x] + g_sr[dB.x];
    float e5 = g_sl[sB.y] + g_sr[dB.y];
    float e6 = g_sl[sB.z] + g_sr[dB.z];
    float e7 = g_sl[sB.w] + g_sr[dB.w];
    e0 = (e0 > 0.f) ? e0 : NEG_SLOPE * e0;
    e1 = (e1 > 0.f) ? e1 : NEG_SLOPE * e1;
    e2 = (e2 > 0.f) ? e2 : NEG_SLOPE * e2;
    e3 = (e3 > 0.f) ? e3 : NEG_SLOPE * e3;
    e4 = (e4 > 0.f) ? e4 : NEG_SLOPE * e4;
    e5 = (e5 > 0.f) ? e5 : NEG_SLOPE * e5;
    e6 = (e6 > 0.f) ? e6 : NEG_SLOPE * e6;
    e7 = (e7 > 0.f) ? e7 : NEG_SLOPE * e7;
    float x0 = __expf(e0), x1 = __expf(e1), x2 = __expf(e2), x3 = __expf(e3);
    float x4 = __expf(e4), x5 = __expf(e5), x6 = __expf(e6), x7 = __expf(e7);

    int p0 = atomicAdd(&g_cur[dA.x], 1);
    int p1 = atomicAdd(&g_cur[dA.y], 1);
    int p2 = atomicAdd(&g_cur[dA.z], 1);
    int p3 = atomicAdd(&g_cur[dA.w], 1);
    int p4 = atomicAdd(&g_cur[dB.x], 1);
    int p5 = atomicAdd(&g_cur[dB.y], 1);
    int p6 = atomicAdd(&g_cur[dB.z], 1);
    int p7 = atomicAdd(&g_cur[dB.w], 1);

    g_ep[p0] = ((ull)__float_as_uint(x0) << 32) | (unsigned)sA.x;
    g_ep[p1] = ((ull)__float_as_uint(x1) << 32) | (unsigned)sA.y;
    g_ep[p2] = ((ull)__float_as_uint(x2) << 32) | (unsigned)sA.z;
    g_ep[p3] = ((ull)__float_as_uint(x3) << 32) | (unsigned)sA.w;
    g_ep[p4] = ((ull)__float_as_uint(x4) << 32) | (unsigned)sB.x;
    g_ep[p5] = ((ull)__float_as_uint(x5) << 32) | (unsigned)sB.y;
    g_ep[p6] = ((ull)__float_as_uint(x6) << 32) | (unsigned)sB.z;
    g_ep[p7] = ((ull)__float_as_uint(x7) << 32) | (unsigned)sB.w;

    atomicAdd(&g_den[dA.x], x0);
    atomicAdd(&g_den[dA.y], x1);
    atomicAdd(&g_den[dA.z], x2);
    atomicAdd(&g_den[dA.w], x3);
    atomicAdd(&g_den[dB.x], x4);
    atomicAdd(&g_den[dB.y], x5);
    atomicAdd(&g_den[dB.z], x6);
    atomicAdd(&g_den[dB.w], x7);
}

// ---------------- node phase: one warp per dst, single pass, unroll 8 ----------------
__global__ void node_kernel(float* __restrict__ out) {
    int gw   = (blockIdx.x * blockDim.x + threadIdx.x) >> 5;
    int lane = threadIdx.x & 31;
    if (gw >= N_NODES) return;
    int beg = g_off[gw];
    int end = g_off[gw + 1];

    float2 acc = make_float2(0.f, 0.f);
    if (beg < end) {
        float invden = 1.0f / g_den[gw];
        int j = beg;
        for (; j + 7 < end; j += 8) {
            ull v0 = g_ep[j],     v1 = g_ep[j + 1];
            ull v2 = g_ep[j + 2], v3 = g_ep[j + 3];
            ull v4 = g_ep[j + 4], v5 = g_ep[j + 5];
            ull v6 = g_ep[j + 6], v7 = g_ep[j + 7];
            int s0 = (int)(v0 & 0xffffffffu), s1 = (int)(v1 & 0xffffffffu);
            int s2 = (int)(v2 & 0xffffffffu), s3 = (int)(v3 & 0xffffffffu);
            int s4 = (int)(v4 & 0xffffffffu), s5 = (int)(v5 & 0xffffffffu);
            int s6 = (int)(v6 & 0xffffffffu), s7 = (int)(v7 & 0xffffffffu);
            float2 z0 = *(const float2*)&g_z[s0 * OUT_DIM + 2 * lane];
            float2 z1 = *(const float2*)&g_z[s1 * OUT_DIM + 2 * lane];
            float2 z2 = *(const float2*)&g_z[s2 * OUT_DIM + 2 * lane];
            float2 z3 = *(const float2*)&g_z[s3 * OUT_DIM + 2 * lane];
            float2 z4 = *(const float2*)&g_z[s4 * OUT_DIM + 2 * lane];
            float2 z5 = *(const float2*)&g_z[s5 * OUT_DIM + 2 * lane];
            float2 z6 = *(const float2*)&g_z[s6 * OUT_DIM + 2 * lane];
            float2 z7 = *(const float2*)&g_z[s7 * OUT_DIM + 2 * lane];
            float a0 = __uint_as_float((uint32_t)(v0 >> 32)) * invden;
            float a1 = __uint_as_float((uint32_t)(v1 >> 32)) * invden;
            float a2 = __uint_as_float((uint32_t)(v2 >> 32)) * invden;
            float a3 = __uint_as_float((uint32_t)(v3 >> 32)) * invden;
            float a4 = __uint_as_float((uint32_t)(v4 >> 32)) * invden;
            float a5 = __uint_as_float((uint32_t)(v5 >> 32)) * invden;
            float a6 = __uint_as_float((uint32_t)(v6 >> 32)) * invden;
            float a7 = __uint_as_float((uint32_t)(v7 >> 32)) * invden;
            acc.x += a0 * z0.x + a1 * z1.x + a2 * z2.x + a3 * z3.x
                   + a4 * z4.x + a5 * z5.x + a6 * z6.x + a7 * z7.x;
            acc.y += a0 * z0.y + a1 * z1.y + a2 * z2.y + a3 * z3.y
                   + a4 * z4.y + a5 * z5.y + a6 * z6.y + a7 * z7.y;
        }
        for (; j < end; ++j) {
            ull v0 = g_ep[j];
            int s0 = (int)(v0 & 0xffffffffu);
            float a0 = __uint_as_float((uint32_t)(v0 >> 32)) * invden;
            float2 z0 = *(const float2*)&g_z[s0 * OUT_DIM + 2 * lane];
            acc.x += a0 * z0.x;
            acc.y += a0 * z0.y;
        }
    }
    *(float2*)&out[gw * OUT_DIM + 2 * lane] = acc;
}

// ---------------- launch: fork-join two streams inside capture ----------------
extern "C" void kernel_launch(void* const* d_in, const int* in_sizes, int n_in,
                              void* d_out, int out_size) {
    const float* h        = (const float*)d_in[0];
    const int*   edge_src = (const int*)d_in[1];
    const int*   edge_dst = (const int*)d_in[2];
    const float* W_fc     = (const float*)d_in[3];
    const float* a_attn   = (const float*)d_in[4];
    float* out = (float*)d_out;

    static cudaStream_t sB = nullptr;
    static cudaEvent_t  evFork = nullptr, evJoin = nullptr;
    if (!sB) {
        cudaStreamCreateWithFlags(&sB, cudaStreamNonBlocking);
        cudaEventCreateWithFlags(&evFork, cudaEventDisableTiming);
        cudaEventCreateWithFlags(&evJoin, cudaEventDisableTiming);
        cudaFuncSetAttribute(gemm_kernel, cudaFuncAttributeMaxDynamicSharedMemorySize, SM_TOTAL);
    }

    // fork: stream B handles the edge-dst-only CSR build
    cudaEventRecord(evFork, 0);
    cudaStreamWaitEvent(sB, evFork, 0);

    zero_kernel<<<(N_NODES + 256) / 256, 256, 0, sB>>>();
    hist_kernel<<<(N_EDGES / 4 + 255) / 256, 256, 0, sB>>>(edge_dst);
    scan_kernel<<<1, 1024, 0, sB>>>();
    cudaEventRecord(evJoin, sB);

    // main stream: W prep then gemm with fused s_l/s_r
    wprep_kernel<<<(IN_DIM * OUT_DIM + 255) / 256, 256>>>(W_fc);
    gemm_kernel<<<(N_NODES + TILE_M - 1) / TILE_M, 256, SM_TOTAL>>>(h, a_attn);

    // join, then the dependent tail
    cudaStreamWaitEvent(0, evJoin, 0);
    scatter_kernel<<<(N_EDGES / 8 + 255) / 256, 256>>>(edge_src, edge_dst);
    node_kernel<<<(N_NODES * 32 + 255) / 256, 256>>>(out);
}